// round 14
// baseline (speedup 1.0000x reference)
#include <cuda_runtime.h>
#include <cuda_fp16.h>
#include <math.h>
#include <cstdint>

// Problem constants
#define BATCH 8
#define CCH   256
#define HH    64
#define WW    160
#define HW    (HH * WW)           // 10240
#define NTOT  (BATCH * CCH * HW)  // 20,971,520
#define NG    (HH / 4)            // 16 row-groups of 4
#define NO    (WW / 8)            // 20 octs per row

// Scratch
__device__ __half g_yh[NTOT];         // y = relu(bn(1x1conv(x))), fp16
__device__ __half g_wh[CCH * CCH];    // fp16(s1[m] * W[m][k]), [m][k]
__device__ float  g_b1[CCH];          // folded BN bias

// ---------------------------------------------------------------------------
__device__ __forceinline__ uint32_t smem_u32(const void* p) {
    uint32_t a;
    asm("{ .reg .u64 t; cvta.to.shared.u64 t, %1; cvt.u32.u64 %0, t; }"
        : "=r"(a) : "l"(p));
    return a;
}
__device__ __forceinline__ void cp16(uint32_t s, const void* g) {
    asm volatile("cp.async.cg.shared.global [%0], [%1], 16;" :: "r"(s), "l"(g));
}
// 8 packed halfs (uint4) -> 8 floats
__device__ __forceinline__ void h8f(float* f, const uint4& u) {
    const __half2* hp = (const __half2*)&u;
    const float2 a = __half22float2(hp[0]);
    const float2 b = __half22float2(hp[1]);
    const float2 c = __half22float2(hp[2]);
    const float2 d = __half22float2(hp[3]);
    f[0] = a.x; f[1] = a.y; f[2] = b.x; f[3] = b.y;
    f[4] = c.x; f[5] = c.y; f[6] = d.x; f[7] = d.y;
}

__global__ void k_nop() {}   // launch-order shim: capture idx 3 -> k_refine

// ---------------------------------------------------------------------------
// K0: fold BN into W (fp16): g_wh[m][k] = fp16(s1[m]*W[m][k]); g_b1[m]
// ---------------------------------------------------------------------------
__global__ void k_tw(const float* __restrict__ W, const float* __restrict__ conv_b,
                     const float* __restrict__ gamma, const float* __restrict__ beta,
                     const float* __restrict__ mean, const float* __restrict__ var) {
    const int m = blockIdx.x, k = threadIdx.x;
    const float s = gamma[m] * rsqrtf(var[m] + 1e-5f);
    g_wh[m * CCH + k] = __float2half_rn(s * W[m * CCH + k]);
    if (k == 0) g_b1[m] = (conv_b[m] - mean[m]) * s + beta[m];
}

// ---------------------------------------------------------------------------
// K1: fp16 mma.sync m16n8k16 GEMM + fused bias + ReLU -> fp16 y
// (unchanged from R12 winner: 128x128 tile, 256 thr, 2 CTAs/SM)
// ---------------------------------------------------------------------------
#define BM      128
#define BK      32
#define BN      128
#define APITCH  40
#define BPITCH  136
#define ASZ     (BM * APITCH)
#define BSZ     (BK * BPITCH)
#define GEMM_SMEM ((2 * ASZ + 2 * BSZ) * 2)   // 37888 B

__global__ __launch_bounds__(256, 2)
void k_gemm(const float* __restrict__ X) {
    extern __shared__ __half smh[];
    __half* As = smh;
    __half* Bs = smh + 2 * ASZ;
    const int tid = threadIdx.x;
    const int wid = tid >> 5, lane = tid & 31;
    const int n0 = blockIdx.x * BN;
    const int m0 = blockIdx.y * BM;
    const int b  = blockIdx.z;
    const uint32_t smbA = smem_u32(As);
    const float* Xb = X + (size_t)b * CCH * HW;

    const int mw = wid >> 2, nw = wid & 3;
    const int lr = lane >> 2, lc = lane & 3;

#pragma unroll
    for (int i = 0; i < 2; ++i) {
        const int idx = tid + i * 256;
        const int row = idx >> 2, c8 = idx & 3;
        cp16(smbA + (row * APITCH + c8 * 8) * 2,
             g_wh + (size_t)(m0 + row) * CCH + c8 * 8);
    }
    asm volatile("cp.async.commit_group;" ::: "memory");
#pragma unroll
    for (int i = 0; i < 4; ++i) {
        const int idx = tid + i * 256;
        const int row = idx >> 5, c4 = idx & 31;
        const float4 v = *(const float4*)(Xb + (size_t)row * HW + n0 + c4 * 4);
        *(__half2*)(Bs + row * BPITCH + c4 * 4)     = __floats2half2_rn(v.x, v.y);
        *(__half2*)(Bs + row * BPITCH + c4 * 4 + 2) = __floats2half2_rn(v.z, v.w);
    }

    float acc[4][4][4];
#pragma unroll
    for (int im = 0; im < 4; ++im)
#pragma unroll
        for (int in = 0; in < 4; ++in)
#pragma unroll
            for (int r = 0; r < 4; ++r) acc[im][in][r] = 0.f;

    for (int kc = 0; kc < 8; ++kc) {
        const int bf = kc & 1;
        asm volatile("cp.async.wait_group 0;" ::: "memory");
        __syncthreads();

        float4 bv[4];
        if (kc < 7) {
            const uint32_t dA = smbA + ((bf ^ 1) * ASZ) * 2;
#pragma unroll
            for (int i = 0; i < 2; ++i) {
                const int idx = tid + i * 256;
                const int row = idx >> 2, c8 = idx & 3;
                cp16(dA + (row * APITCH + c8 * 8) * 2,
                     g_wh + (size_t)(m0 + row) * CCH + (kc + 1) * BK + c8 * 8);
            }
            asm volatile("cp.async.commit_group;" ::: "memory");
#pragma unroll
            for (int i = 0; i < 4; ++i) {
                const int idx = tid + i * 256;
                const int row = idx >> 5, c4 = idx & 31;
                bv[i] = *(const float4*)(Xb + (size_t)((kc + 1) * BK + row) * HW
                                         + n0 + c4 * 4);
            }
        }

        const __half* Ab = As + bf * ASZ;
        const uint32_t bB = smem_u32(Bs) + (bf * BSZ) * 2;
#pragma unroll
        for (int ks = 0; ks < 2; ++ks) {
            uint32_t a[4][4], bfr[4][2];
#pragma unroll
            for (int im = 0; im < 4; ++im) {
                const int m = mw * 64 + im * 16 + lr;
                const __half* ap = Ab + m * APITCH + ks * 16 + lc * 2;
                a[im][0] = *(const uint32_t*)(ap);
                a[im][1] = *(const uint32_t*)(ap + 8 * APITCH);
                a[im][2] = *(const uint32_t*)(ap + 8);
                a[im][3] = *(const uint32_t*)(ap + 8 * APITCH + 8);
            }
#pragma unroll
            for (int in = 0; in < 4; ++in) {
                const uint32_t addr = bB +
                    ((ks * 16 + (lane & 15)) * BPITCH + nw * 32 + in * 8) * 2;
                asm volatile(
                    "ldmatrix.sync.aligned.m8n8.x2.trans.shared.b16 {%0,%1}, [%2];"
                    : "=r"(bfr[in][0]), "=r"(bfr[in][1]) : "r"(addr));
            }
#pragma unroll
            for (int im = 0; im < 4; ++im)
#pragma unroll
                for (int in = 0; in < 4; ++in) {
                    asm volatile(
                        "mma.sync.aligned.m16n8k16.row.col.f32.f16.f16.f32 "
                        "{%0,%1,%2,%3}, {%4,%5,%6,%7}, {%8,%9}, {%0,%1,%2,%3};"
                        : "+f"(acc[im][in][0]), "+f"(acc[im][in][1]),
                          "+f"(acc[im][in][2]), "+f"(acc[im][in][3])
                        : "r"(a[im][0]), "r"(a[im][1]), "r"(a[im][2]), "r"(a[im][3]),
                          "r"(bfr[in][0]), "r"(bfr[in][1]));
                }
        }

        if (kc < 7) {
            __half* Bd = Bs + (bf ^ 1) * BSZ;
#pragma unroll
            for (int i = 0; i < 4; ++i) {
                const int idx = tid + i * 256;
                const int row = idx >> 5, c4 = idx & 31;
                *(__half2*)(Bd + row * BPITCH + c4 * 4)     = __floats2half2_rn(bv[i].x, bv[i].y);
                *(__half2*)(Bd + row * BPITCH + c4 * 4 + 2) = __floats2half2_rn(bv[i].z, bv[i].w);
            }
        }
    }

#pragma unroll
    for (int im = 0; im < 4; ++im) {
        const int r0 = m0 + mw * 64 + im * 16 + lr;
        const float bz0 = g_b1[r0], bz1 = g_b1[r0 + 8];
#pragma unroll
        for (int in = 0; in < 4; ++in) {
            const int nc = n0 + nw * 32 + in * 8 + lc * 2;
            __half* p0 = g_yh + ((size_t)(b * CCH + r0)) * HW + nc;
            __half* p1 = p0 + (size_t)8 * HW;
            *(__half2*)p0 = __floats2half2_rn(fmaxf(acc[im][in][0] + bz0, 0.f),
                                              fmaxf(acc[im][in][1] + bz0, 0.f));
            *(__half2*)p1 = __floats2half2_rn(fmaxf(acc[im][in][2] + bz1, 0.f),
                                              fmaxf(acc[im][in][3] + bz1, 0.f));
        }
    }
}

// ---------------------------------------------------------------------------
// K2: refine, 8-wide strips (halved LSU wavefront count).
//   phase Z:   4x8 strips, rolling 3-row window of 10-float rows
//   phase ACC: rolling vertical accumulation, one uint4 z-load per row
//   phase BORDER: 444 px masked formula.
// ---------------------------------------------------------------------------
#define REFINE_SMEM (HW * 2)

__device__ __forceinline__ void load_row8(float* w, const __half* ypl,
                                          const uint4* yo, int r, int o,
                                          int cl, int cr) {
    w[0] = __half2float(ypl[r * WW + cl]);
    h8f(w + 1, yo[r * NO + o]);
    w[9] = __half2float(ypl[r * WW + cr]);
}
__device__ __forceinline__ void row_acc8(float* z, const float* gr, const float* w) {
#pragma unroll
    for (int j = 0; j < 8; ++j) {
        z[j] = fmaf(gr[0], w[j],     z[j]);
        z[j] = fmaf(gr[1], w[j + 1], z[j]);
        z[j] = fmaf(gr[2], w[j + 2], z[j]);
    }
}

__global__ __launch_bounds__(256, 3)
void k_refine(const float* __restrict__ x,
              const float* __restrict__ rw, const float* __restrict__ rbias,
              const float* __restrict__ rg, const float* __restrict__ rbeta,
              const float* __restrict__ rmu, const float* __restrict__ rvar,
              float* __restrict__ out,
              float w1, float w2, float w3) {
    extern __shared__ __half zp[];           // z plane, fp16, 20 KB
    uint4* zq4 = (uint4*)zp;                 // 8-half octs

    const int bc = blockIdx.x;
    const int c  = bc & 255;
    const int tid = threadIdx.x;
    const __half* __restrict__ ypl = g_yh + (size_t)bc * HW;
    const uint4* __restrict__ yo  = (const uint4*)ypl;

    const float rs  = rg[c] * rsqrtf(rvar[c] + 1e-5f);
    const float rbb = (rbias[c] - rmu[c]) * rs + rbeta[c];
    float g[3][3];
#pragma unroll
    for (int k = 0; k < 9; ++k) ((float*)g)[k] = rs * __ldg(rw + c * 9 + k);
    const float wts[4] = {0.f, w1, w2, w3};

    // ---- phase Z: 4x8 strips, rolling 3-row window ----
    for (int it = tid; it < NG * NO; it += 256) {
        const int g4 = it / NO;
        const int o  = it - g4 * NO;
        const int h0 = g4 << 2;
        const int col0 = o * 8;
        const int cl = (col0 + WW - 1) % WW;
        const int cr = (col0 + 8) % WW;

        float wA[10], wB[10], wC[10];
        load_row8(wA, ypl, yo, (h0 + HH - 1) & (HH - 1), o, cl, cr);
        load_row8(wB, ypl, yo, h0, o, cl, cr);
#pragma unroll
        for (int i = 0; i < 4; ++i) {
            load_row8(wC, ypl, yo, (h0 + i + 1) & (HH - 1), o, cl, cr);
            float z[8];
#pragma unroll
            for (int j = 0; j < 8; ++j) z[j] = rbb;
            row_acc8(z, g[0], wA);
            row_acc8(z, g[1], wB);
            row_acc8(z, g[2], wC);
            uint4 zo;
            __half2* hp = (__half2*)&zo;
            hp[0] = __floats2half2_rn(fmaxf(z[0], 0.f), fmaxf(z[1], 0.f));
            hp[1] = __floats2half2_rn(fmaxf(z[2], 0.f), fmaxf(z[3], 0.f));
            hp[2] = __floats2half2_rn(fmaxf(z[4], 0.f), fmaxf(z[5], 0.f));
            hp[3] = __floats2half2_rn(fmaxf(z[6], 0.f), fmaxf(z[7], 0.f));
            zq4[(h0 + i) * NO + o] = zo;
#pragma unroll
            for (int j = 0; j < 10; ++j) { wA[j] = wB[j]; wB[j] = wC[j]; }
        }
    }
    __syncthreads();

    // ---- phase ACC: rolling vertical accumulation + center-row horizontal ----
    for (int it = tid; it < NG * NO; it += 256) {
        const int g4 = it / NO;
        const int o  = it - g4 * NO;
        const int h0 = g4 << 2;
        const int col0 = o * 8;
        const int ol = o ? o - 1 : NO - 1;
        const int orr = (o == NO - 1) ? 0 : o + 1;

        float acc[4][8];
#pragma unroll
        for (int i = 0; i < 4; ++i)
#pragma unroll
            for (int k = 0; k < 8; ++k) acc[i][k] = 0.f;

#pragma unroll
        for (int j = 0; j < 10; ++j) {          // z rows h0-3 .. h0+6
            const int hr = (h0 - 3 + j) & (HH - 1);
            float f[8];
            h8f(f, zq4[hr * NO + o]);
#pragma unroll
            for (int i = 0; i < 4; ++i) {
                const int s = j - 3 - i;        // vertical shift
                const int as = s < 0 ? -s : s;
                if (as >= 1 && as <= 3) {
                    const float wt = wts[as];
#pragma unroll
                    for (int k = 0; k < 8; ++k)
                        acc[i][k] = fmaf(wt, f[k], acc[i][k]);
                }
            }
            if (j >= 3 && j <= 6) {             // this row is output row i=j-3
                const int i = j - 3;
                const uint4 lz = zq4[hr * NO + ol];
                const uint4 rz = zq4[hr * NO + orr];
                const __half2* lp = (const __half2*)&lz;
                const __half2* rp = (const __half2*)&rz;
                float w14[14];
                w14[0] = __half2float(__high2half(lp[2]));
                const float2 l3 = __half22float2(lp[3]);
                w14[1] = l3.x; w14[2] = l3.y;
#pragma unroll
                for (int k = 0; k < 8; ++k) w14[3 + k] = f[k];
                const float2 r0 = __half22float2(rp[0]);
                w14[11] = r0.x; w14[12] = r0.y;
                w14[13] = __half2float(__low2half(rp[1]));
#pragma unroll
                for (int s = 1; s <= 3; ++s) {
                    const float wt = wts[s];
#pragma unroll
                    for (int k = 0; k < 8; ++k)
                        acc[i][k] = fmaf(wt, w14[3 + k - s] + w14[3 + k + s],
                                         acc[i][k]);
                }
            }
        }

        // output
#pragma unroll
        for (int i = 0; i < 4; ++i) {
            const int hh = h0 + i;
            if (hh < 1 || hh > HH - 2) continue;
            const size_t base = (size_t)bc * HW + hh * WW + col0;
            const float4 x0 = *(const float4*)(x + base);
            const float4 x1 = *(const float4*)(x + base + 4);
            float4 o0, o1;
            o0.x = x0.x + acc[i][0]; o0.y = x0.y + acc[i][1];
            o0.z = x0.z + acc[i][2]; o0.w = x0.w + acc[i][3];
            o1.x = x1.x + acc[i][4]; o1.y = x1.y + acc[i][5];
            o1.z = x1.z + acc[i][6]; o1.w = x1.w + acc[i][7];
            if (o > 0) *(float4*)(out + base) = o0;
            else { out[base + 1] = o0.y; out[base + 2] = o0.z; out[base + 3] = o0.w; }
            if (o < NO - 1) *(float4*)(out + base + 4) = o1;
            else { out[base + 4] = o1.x; out[base + 5] = o1.y; out[base + 6] = o1.z; }
        }
    }

    // ---- phase BORDER: 444 true-border px, masked formula, y(fp16) ----
    for (int i = tid; i < 2 * WW + 2 * (HH - 2); i += 256) {
        int h, wj;
        if (i < 2 * WW) { h = (i < WW) ? 0 : HH - 1; wj = (i < WW) ? i : i - WW; }
        else { const int j = i - 2 * WW; h = 1 + (j >> 1); wj = (j & 1) ? WW - 1 : 0; }

        const int SHV[12] = {1, 2, 3, -1, -2, -3, 0, 0, 0, 0, 0, 0};
        const int SWV[12] = {0, 0, 0, 0, 0, 0, -1, -2, -3, 1, 2, 3};
        const int AW[12]  = {1, 2, 3, 1, 2, 3, 1, 2, 3, 1, 2, 3};
        const float rv0 = (h >= 1) ? 1.f : 0.f;
        const float rv2 = (h <= HH - 2) ? 1.f : 0.f;
        const float cv0 = (wj >= 1) ? 1.f : 0.f;
        const float cv2 = (wj <= WW - 2) ? 1.f : 0.f;
        float gm[3][3];
#pragma unroll
        for (int kw = 0; kw < 3; ++kw) {
            const float cv = (kw == 0) ? cv0 : (kw == 2) ? cv2 : 1.f;
            gm[0][kw] = g[0][kw] * rv0 * cv;
            gm[1][kw] = g[1][kw] * cv;
            gm[2][kw] = g[2][kw] * rv2 * cv;
        }
        float a = 0.f;
#pragma unroll
        for (int si = 0; si < 12; ++si) {
            const int sh = SHV[si], sw = SWV[si];
            float sum = 0.f;
#pragma unroll
            for (int kh = 0; kh < 3; ++kh)
#pragma unroll
                for (int kw = 0; kw < 3; ++kw) {
                    const int rr = (h + kh - 1 - sh) & (HH - 1);
                    int ccol = wj + kw - 1 - sw;
                    if (ccol < 0) ccol += WW;
                    if (ccol >= WW) ccol -= WW;
                    sum = fmaf(gm[kh][kw], __half2float(ypl[rr * WW + ccol]), sum);
                }
            a = fmaf(wts[AW[si]], fmaxf(sum + rbb, 0.f), a);
        }
        const size_t base = (size_t)bc * HW + h * WW + wj;
        out[base] = x[base] + a;
    }
}

// ---------------------------------------------------------------------------
extern "C" void kernel_launch(void* const* d_in, const int* in_sizes, int n_in,
                              void* d_out, int out_size) {
    const float* x        = (const float*)d_in[0];
    const float* conv_w   = (const float*)d_in[1];
    const float* conv_b   = (const float*)d_in[2];
    const float* bn_gamma = (const float*)d_in[3];
    const float* bn_beta  = (const float*)d_in[4];
    const float* bn_mean  = (const float*)d_in[5];
    const float* bn_var   = (const float*)d_in[6];
    const float* refine_w = (const float*)d_in[7];
    const float* refine_b = (const float*)d_in[8];
    const float* rbn_gamma = (const float*)d_in[9];
    const float* rbn_beta  = (const float*)d_in[10];
    const float* rbn_mean  = (const float*)d_in[11];
    const float* rbn_var   = (const float*)d_in[12];
    float* out = (float*)d_out;

    const double s2 = 2.0 * 1.5 * 1.5;
    const double e1 = exp(-1.0 / s2), e2 = exp(-4.0 / s2), e3 = exp(-9.0 / s2);
    const double wsum = 4.0 * (e1 + e2 + e3);
    const float w1 = (float)(0.5 * e1 / wsum);
    const float w2 = (float)(0.5 * e2 / wsum);
    const float w3 = (float)(0.5 * e3 / wsum);

    cudaFuncSetAttribute(k_gemm, cudaFuncAttributeMaxDynamicSharedMemorySize,
                         GEMM_SMEM);
    cudaFuncSetAttribute(k_refine, cudaFuncAttributeMaxDynamicSharedMemorySize,
                         REFINE_SMEM);

    // order: capture index 3 lands on k_refine (verify LSU-wavefront theory)
    k_nop<<<1, 32>>>();

    k_tw<<<CCH, CCH>>>(conv_w, conv_b, bn_gamma, bn_beta, bn_mean, bn_var);

    dim3 gg(HW / BN, CCH / BM, BATCH);   // (80, 2, 8)
    k_gemm<<<gg, 256, GEMM_SMEM>>>(x);

    k_refine<<<BATCH * CCH, 256, REFINE_SMEM>>>(x, refine_w, refine_b,
                                                rbn_gamma, rbn_beta, rbn_mean,
                                                rbn_var, out, w1, w2, w3);
}

// round 15
// speedup vs baseline: 1.0660x; 1.0660x over previous
#include <cuda_runtime.h>
#include <cuda_fp16.h>
#include <math.h>
#include <cstdint>

// Problem constants
#define BATCH 8
#define CCH   256
#define HH    64
#define WW    160
#define HW    (HH * WW)           // 10240
#define NTOT  (BATCH * CCH * HW)  // 20,971,520
#define NQ    (WW / 4)            // 40 quads per row
#define NG    (HH / 4)            // 16 row-groups of 4

// Scratch
__device__ __half g_yh[NTOT];         // y = relu(bn(1x1conv(x))), fp16
__device__ __half g_wh[CCH * CCH];    // fp16(s1[m] * W[m][k]), [m][k]
__device__ float  g_b1[CCH];          // folded BN bias

// ---------------------------------------------------------------------------
__device__ __forceinline__ uint32_t smem_u32(const void* p) {
    uint32_t a;
    asm("{ .reg .u64 t; cvta.to.shared.u64 t, %1; cvt.u32.u64 %0, t; }"
        : "=r"(a) : "l"(p));
    return a;
}
__device__ __forceinline__ void cp16(uint32_t s, const void* g) {
    asm volatile("cp.async.cg.shared.global [%0], [%1], 16;" :: "r"(s), "l"(g));
}
// 4 packed halfs -> float4
__device__ __forceinline__ float4 h4f(uint2 u) {
    const float2 a = __half22float2(*(const __half2*)&u.x);
    const float2 b = __half22float2(*(const __half2*)&u.y);
    return make_float4(a.x, a.y, b.x, b.y);
}

__global__ void k_nop() {}   // launch-order shims: capture idx 3 -> k_gemm

// ---------------------------------------------------------------------------
// K0: fold BN into W (fp16): g_wh[m][k] = fp16(s1[m]*W[m][k]); g_b1[m]
// ---------------------------------------------------------------------------
__global__ void k_tw(const float* __restrict__ W, const float* __restrict__ conv_b,
                     const float* __restrict__ gamma, const float* __restrict__ beta,
                     const float* __restrict__ mean, const float* __restrict__ var) {
    const int m = blockIdx.x, k = threadIdx.x;
    const float s = gamma[m] * rsqrtf(var[m] + 1e-5f);
    g_wh[m * CCH + k] = __float2half_rn(s * W[m * CCH + k]);
    if (k == 0) g_b1[m] = (conv_b[m] - mean[m]) * s + beta[m];
}

// ---------------------------------------------------------------------------
// K1: fp16 mma.sync m16n8k16 GEMM + fused bias + ReLU -> fp16 y
// 128x128 tile, 256 thr, 2 CTAs/SM. A-frags now via ldmatrix.x4
// (4x fewer issue slots on the A path vs 16x LDS.32). grid (80, 2, 8).
// ---------------------------------------------------------------------------
#define BM      128
#define BK      32
#define BN      128
#define APITCH  40
#define BPITCH  136
#define ASZ     (BM * APITCH)
#define BSZ     (BK * BPITCH)
#define GEMM_SMEM ((2 * ASZ + 2 * BSZ) * 2)   // 37888 B

__global__ __launch_bounds__(256, 2)
void k_gemm(const float* __restrict__ X) {
    extern __shared__ __half smh[];
    __half* As = smh;                // 2 buffers [BM][APITCH]
    __half* Bs = smh + 2 * ASZ;      // 2 buffers [BK][BPITCH]
    const int tid = threadIdx.x;
    const int wid = tid >> 5, lane = tid & 31;
    const int n0 = blockIdx.x * BN;
    const int m0 = blockIdx.y * BM;
    const int b  = blockIdx.z;
    const uint32_t smbA = smem_u32(As);
    const uint32_t smbB = smem_u32(Bs);
    const float* Xb = X + (size_t)b * CCH * HW;

    const int mw = wid >> 2, nw = wid & 3;       // 2m x 4n warp grid
    const int lr = lane >> 2, lc = lane & 3;
    // ldmatrix.x4 lane->address decomposition (A fragments)
    const int lm_r = lane & 7;                    // row within 8x8 matrix
    const int lm_m = (lane >> 3) & 1;             // +8 rows for matrices 1,3
    const int lm_k = (lane >> 4) & 1;             // +8 cols for matrices 2,3

    // ---- prologue: A tile 0 (cp.async), B tile 0 (LDG+cvt+STS) ----
#pragma unroll
    for (int i = 0; i < 2; ++i) {
        const int idx = tid + i * 256;           // 0..511
        const int row = idx >> 2, c8 = idx & 3;
        cp16(smbA + (row * APITCH + c8 * 8) * 2,
             g_wh + (size_t)(m0 + row) * CCH + c8 * 8);
    }
    asm volatile("cp.async.commit_group;" ::: "memory");
#pragma unroll
    for (int i = 0; i < 4; ++i) {
        const int idx = tid + i * 256;           // 0..1023
        const int row = idx >> 5, c4 = idx & 31;
        const float4 v = *(const float4*)(Xb + (size_t)row * HW + n0 + c4 * 4);
        *(__half2*)(Bs + row * BPITCH + c4 * 4)     = __floats2half2_rn(v.x, v.y);
        *(__half2*)(Bs + row * BPITCH + c4 * 4 + 2) = __floats2half2_rn(v.z, v.w);
    }

    float acc[4][4][4];
#pragma unroll
    for (int im = 0; im < 4; ++im)
#pragma unroll
        for (int in = 0; in < 4; ++in)
#pragma unroll
            for (int r = 0; r < 4; ++r) acc[im][in][r] = 0.f;

    for (int kc = 0; kc < 8; ++kc) {
        const int bf = kc & 1;
        asm volatile("cp.async.wait_group 0;" ::: "memory");
        __syncthreads();

        float4 bv[4];
        if (kc < 7) {
            const uint32_t dA = smbA + ((bf ^ 1) * ASZ) * 2;
#pragma unroll
            for (int i = 0; i < 2; ++i) {
                const int idx = tid + i * 256;
                const int row = idx >> 2, c8 = idx & 3;
                cp16(dA + (row * APITCH + c8 * 8) * 2,
                     g_wh + (size_t)(m0 + row) * CCH + (kc + 1) * BK + c8 * 8);
            }
            asm volatile("cp.async.commit_group;" ::: "memory");
#pragma unroll
            for (int i = 0; i < 4; ++i) {
                const int idx = tid + i * 256;
                const int row = idx >> 5, c4 = idx & 31;
                bv[i] = *(const float4*)(Xb + (size_t)((kc + 1) * BK + row) * HW
                                         + n0 + c4 * 4);
            }
        }

        const uint32_t aB = smbA + (bf * ASZ) * 2;
        const uint32_t bB = smbB + (bf * BSZ) * 2;
#pragma unroll
        for (int ks = 0; ks < 2; ++ks) {
            uint32_t a[4][4], bfr[4][2];
#pragma unroll
            for (int im = 0; im < 4; ++im) {
                const int row = mw * 64 + im * 16 + lm_m * 8 + lm_r;
                const int col = ks * 16 + lm_k * 8;
                const uint32_t addr = aB + (row * APITCH + col) * 2;
                asm volatile(
                    "ldmatrix.sync.aligned.m8n8.x4.shared.b16 {%0,%1,%2,%3}, [%4];"
                    : "=r"(a[im][0]), "=r"(a[im][1]), "=r"(a[im][2]), "=r"(a[im][3])
                    : "r"(addr));
            }
#pragma unroll
            for (int in = 0; in < 4; ++in) {
                const uint32_t addr = bB +
                    ((ks * 16 + (lane & 15)) * BPITCH + nw * 32 + in * 8) * 2;
                asm volatile(
                    "ldmatrix.sync.aligned.m8n8.x2.trans.shared.b16 {%0,%1}, [%2];"
                    : "=r"(bfr[in][0]), "=r"(bfr[in][1]) : "r"(addr));
            }
#pragma unroll
            for (int im = 0; im < 4; ++im)
#pragma unroll
                for (int in = 0; in < 4; ++in) {
                    asm volatile(
                        "mma.sync.aligned.m16n8k16.row.col.f32.f16.f16.f32 "
                        "{%0,%1,%2,%3}, {%4,%5,%6,%7}, {%8,%9}, {%0,%1,%2,%3};"
                        : "+f"(acc[im][in][0]), "+f"(acc[im][in][1]),
                          "+f"(acc[im][in][2]), "+f"(acc[im][in][3])
                        : "r"(a[im][0]), "r"(a[im][1]), "r"(a[im][2]), "r"(a[im][3]),
                          "r"(bfr[in][0]), "r"(bfr[in][1]));
                }
        }

        if (kc < 7) {
            __half* Bd = Bs + (bf ^ 1) * BSZ;
#pragma unroll
            for (int i = 0; i < 4; ++i) {
                const int idx = tid + i * 256;
                const int row = idx >> 5, c4 = idx & 31;
                *(__half2*)(Bd + row * BPITCH + c4 * 4)     = __floats2half2_rn(bv[i].x, bv[i].y);
                *(__half2*)(Bd + row * BPITCH + c4 * 4 + 2) = __floats2half2_rn(bv[i].z, bv[i].w);
            }
        }
    }

    // epilogue: bias + ReLU -> fp16 y
#pragma unroll
    for (int im = 0; im < 4; ++im) {
        const int r0 = m0 + mw * 64 + im * 16 + lr;
        const float bz0 = g_b1[r0], bz1 = g_b1[r0 + 8];
#pragma unroll
        for (int in = 0; in < 4; ++in) {
            const int nc = n0 + nw * 32 + in * 8 + lc * 2;
            __half* p0 = g_yh + ((size_t)(b * CCH + r0)) * HW + nc;
            __half* p1 = p0 + (size_t)8 * HW;
            *(__half2*)p0 = __floats2half2_rn(fmaxf(acc[im][in][0] + bz0, 0.f),
                                              fmaxf(acc[im][in][1] + bz0, 0.f));
            *(__half2*)p1 = __floats2half2_rn(fmaxf(acc[im][in][2] + bz1, 0.f),
                                              fmaxf(acc[im][in][3] + bz1, 0.f));
        }
    }
}

// ---------------------------------------------------------------------------
// K2: refine — exact R12 version (validated 69 us): y fp16 from GMEM,
// z fp16 in smem (20 KB), 4-row strips, 10-row z column.
// ---------------------------------------------------------------------------
#define REFINE_SMEM (HW * 2)

__device__ __forceinline__ void row_acc(float z[4], const float* gr,
                                        const float4& L, const float4& C,
                                        const float4& R) {
    const float w6[6] = {L.w, C.x, C.y, C.z, C.w, R.x};
#pragma unroll
    for (int j = 0; j < 4; ++j) {
        z[j] = fmaf(gr[0], w6[j],     z[j]);
        z[j] = fmaf(gr[1], w6[j + 1], z[j]);
        z[j] = fmaf(gr[2], w6[j + 2], z[j]);
    }
}

__global__ __launch_bounds__(256, 4)
void k_refine(const float* __restrict__ x,
              const float* __restrict__ rw, const float* __restrict__ rbias,
              const float* __restrict__ rg, const float* __restrict__ rbeta,
              const float* __restrict__ rmu, const float* __restrict__ rvar,
              float* __restrict__ out,
              float w1, float w2, float w3) {
    extern __shared__ __half zp[];           // z plane, fp16, 20 KB
    uint2* zq2 = (uint2*)zp;                 // 4-half quads

    const int bc = blockIdx.x;
    const int c  = bc & 255;
    const int tid = threadIdx.x;
    const __half* __restrict__ ypl = g_yh + (size_t)bc * HW;
    const uint2* __restrict__ yq  = (const uint2*)ypl;

    const float rs  = rg[c] * rsqrtf(rvar[c] + 1e-5f);
    const float rbb = (rbias[c] - rmu[c]) * rs + rbeta[c];
    float g[3][3];
#pragma unroll
    for (int k = 0; k < 9; ++k) ((float*)g)[k] = rs * __ldg(rw + c * 9 + k);
    const float wts[4] = {0.f, w1, w2, w3};

    // ---- phase Z: 4-row strips, rolling 3-row window, y(fp16) -> z(fp16) ----
    for (int it = tid; it < NG * NQ; it += 256) {
        const int g4 = it / NQ;
        const int wq = it - g4 * NQ;
        const int h0 = g4 << 2;
        const int ql = wq ? wq - 1 : NQ - 1;
        const int qr = (wq == NQ - 1) ? 0 : wq + 1;

        float4 La, Ca, Ra, Lb, Cb, Rb;
        {
            const int rm = (h0 + HH - 1) & (HH - 1);
            La = h4f(yq[rm * NQ + ql]); Ca = h4f(yq[rm * NQ + wq]); Ra = h4f(yq[rm * NQ + qr]);
            Lb = h4f(yq[h0 * NQ + ql]); Cb = h4f(yq[h0 * NQ + wq]); Rb = h4f(yq[h0 * NQ + qr]);
        }
#pragma unroll
        for (int i = 0; i < 4; ++i) {
            const int rn = (h0 + i + 1) & (HH - 1);
            const float4 Lc = h4f(yq[rn * NQ + ql]);
            const float4 Cc = h4f(yq[rn * NQ + wq]);
            const float4 Rc = h4f(yq[rn * NQ + qr]);
            float z[4] = {rbb, rbb, rbb, rbb};
            row_acc(z, g[0], La, Ca, Ra);
            row_acc(z, g[1], Lb, Cb, Rb);
            row_acc(z, g[2], Lc, Cc, Rc);
            uint2 zo;
            *(__half2*)&zo.x = __floats2half2_rn(fmaxf(z[0], 0.f), fmaxf(z[1], 0.f));
            *(__half2*)&zo.y = __floats2half2_rn(fmaxf(z[2], 0.f), fmaxf(z[3], 0.f));
            zq2[(h0 + i) * NQ + wq] = zo;
            La = Lb; Ca = Cb; Ra = Rb;
            Lb = Lc; Cb = Cc; Rb = Rc;
        }
    }
    __syncthreads();

    // ---- phase ACC: 4-row strips, 10-row z column (uint2, cvt on use) ----
    for (int it = tid; it < NG * NQ; it += 256) {
        const int g4 = it / NQ;
        const int wq = it - g4 * NQ;
        const int h0 = g4 << 2;
        const int ql = wq ? wq - 1 : NQ - 1;
        const int qr = (wq == NQ - 1) ? 0 : wq + 1;

        uint2 zv[10];
#pragma unroll
        for (int j = 0; j < 10; ++j)
            zv[j] = zq2[((h0 - 3 + j) & (HH - 1)) * NQ + wq];

#pragma unroll
        for (int i = 0; i < 4; ++i) {
            float acc[4] = {0.f, 0.f, 0.f, 0.f};
#pragma unroll
            for (int s = 1; s <= 3; ++s) {
                const float wt = wts[s];
                const float4 u = h4f(zv[i + 3 - s]);
                const float4 d = h4f(zv[i + 3 + s]);
                acc[0] = fmaf(wt, u.x + d.x, acc[0]);
                acc[1] = fmaf(wt, u.y + d.y, acc[1]);
                acc[2] = fmaf(wt, u.z + d.z, acc[2]);
                acc[3] = fmaf(wt, u.w + d.w, acc[3]);
            }
            const int hh = h0 + i;
            float zr[12];
            *(float4*)(zr)     = h4f(zq2[hh * NQ + ql]);
            *(float4*)(zr + 4) = h4f(zv[i + 3]);
            *(float4*)(zr + 8) = h4f(zq2[hh * NQ + qr]);
#pragma unroll
            for (int s = 1; s <= 3; ++s) {
                const float wt = wts[s];
#pragma unroll
                for (int j = 0; j < 4; ++j)
                    acc[j] = fmaf(wt, zr[4 + j - s] + zr[4 + j + s], acc[j]);
            }
            const size_t base = (size_t)bc * HW + hh * WW + wq * 4;
            const float4 xv = *(const float4*)(x + base);
            float4 o4;
            o4.x = xv.x + acc[0]; o4.y = xv.y + acc[1];
            o4.z = xv.z + acc[2]; o4.w = xv.w + acc[3];
            if (hh >= 1 && hh <= HH - 2 && wq >= 1 && wq <= NQ - 2) {
                *(float4*)(out + base) = o4;
            } else {
#pragma unroll
                for (int j = 0; j < 4; ++j) {
                    const int wj = wq * 4 + j;
                    if (hh >= 1 && hh <= HH - 2 && wj >= 1 && wj <= WW - 2)
                        out[base + j] = ((const float*)&o4)[j];
                }
            }
        }
    }

    // ---- phase BORDER: 444 true-border px, masked formula, y(fp16) ----
    for (int i = tid; i < 2 * WW + 2 * (HH - 2); i += 256) {
        int h, wj;
        if (i < 2 * WW) { h = (i < WW) ? 0 : HH - 1; wj = (i < WW) ? i : i - WW; }
        else { const int j = i - 2 * WW; h = 1 + (j >> 1); wj = (j & 1) ? WW - 1 : 0; }

        const int SHV[12] = {1, 2, 3, -1, -2, -3, 0, 0, 0, 0, 0, 0};
        const int SWV[12] = {0, 0, 0, 0, 0, 0, -1, -2, -3, 1, 2, 3};
        const int AW[12]  = {1, 2, 3, 1, 2, 3, 1, 2, 3, 1, 2, 3};
        const float rv0 = (h >= 1) ? 1.f : 0.f;
        const float rv2 = (h <= HH - 2) ? 1.f : 0.f;
        const float cv0 = (wj >= 1) ? 1.f : 0.f;
        const float cv2 = (wj <= WW - 2) ? 1.f : 0.f;
        float gm[3][3];
#pragma unroll
        for (int kw = 0; kw < 3; ++kw) {
            const float cv = (kw == 0) ? cv0 : (kw == 2) ? cv2 : 1.f;
            gm[0][kw] = g[0][kw] * rv0 * cv;
            gm[1][kw] = g[1][kw] * cv;
            gm[2][kw] = g[2][kw] * rv2 * cv;
        }
        float a = 0.f;
#pragma unroll
        for (int si = 0; si < 12; ++si) {
            const int sh = SHV[si], sw = SWV[si];
            float sum = 0.f;
#pragma unroll
            for (int kh = 0; kh < 3; ++kh)
#pragma unroll
                for (int kw = 0; kw < 3; ++kw) {
                    const int rr = (h + kh - 1 - sh) & (HH - 1);
                    int ccol = wj + kw - 1 - sw;
                    if (ccol < 0) ccol += WW;
                    if (ccol >= WW) ccol -= WW;
                    sum = fmaf(gm[kh][kw], __half2float(ypl[rr * WW + ccol]), sum);
                }
            a = fmaf(wts[AW[si]], fmaxf(sum + rbb, 0.f), a);
        }
        const size_t base = (size_t)bc * HW + h * WW + wj;
        out[base] = x[base] + a;
    }
}

// ---------------------------------------------------------------------------
extern "C" void kernel_launch(void* const* d_in, const int* in_sizes, int n_in,
                              void* d_out, int out_size) {
    const float* x        = (const float*)d_in[0];
    const float* conv_w   = (const float*)d_in[1];
    const float* conv_b   = (const float*)d_in[2];
    const float* bn_gamma = (const float*)d_in[3];
    const float* bn_beta  = (const float*)d_in[4];
    const float* bn_mean  = (const float*)d_in[5];
    const float* bn_var   = (const float*)d_in[6];
    const float* refine_w = (const float*)d_in[7];
    const float* refine_b = (const float*)d_in[8];
    const float* rbn_gamma = (const float*)d_in[9];
    const float* rbn_beta  = (const float*)d_in[10];
    const float* rbn_mean  = (const float*)d_in[11];
    const float* rbn_var   = (const float*)d_in[12];
    float* out = (float*)d_out;

    const double s2 = 2.0 * 1.5 * 1.5;
    const double e1 = exp(-1.0 / s2), e2 = exp(-4.0 / s2), e3 = exp(-9.0 / s2);
    const double wsum = 4.0 * (e1 + e2 + e3);
    const float w1 = (float)(0.5 * e1 / wsum);
    const float w2 = (float)(0.5 * e2 / wsum);
    const float w3 = (float)(0.5 * e3 / wsum);

    cudaFuncSetAttribute(k_gemm, cudaFuncAttributeMaxDynamicSharedMemorySize,
                         GEMM_SMEM);
    cudaFuncSetAttribute(k_refine, cudaFuncAttributeMaxDynamicSharedMemorySize,
                         REFINE_SMEM);

    // order: capture index 3 lands on k_gemm (verify ldmatrix-A issue theory)
    k_nop<<<1, 32>>>();
    k_nop<<<1, 32>>>();

    k_tw<<<CCH, CCH>>>(conv_w, conv_b, bn_gamma, bn_beta, bn_mean, bn_var);

    dim3 gg(HW / BN, CCH / BM, BATCH);   // (80, 2, 8)
    k_gemm<<<gg, 256, GEMM_SMEM>>>(x);

    k_refine<<<BATCH * CCH, 256, REFINE_SMEM>>>(x, refine_w, refine_b,
                                                rbn_gamma, rbn_beta, rbn_mean,
                                                rbn_var, out, w1, w2, w3);
}